// round 7
// baseline (speedup 1.0000x reference)
#include <cuda_runtime.h>

// ---------------------------------------------------------------------------
// OmniSuperPointTransformer: gather + pos-MLP (3->32 LN ReLU 32->32) +
// fused segment-mean scatter into superpoints.
//
// Key ideas:
//  * smean(x) + smean(x_pos) == segsum(x + x_pos) / denom  (same denominator)
//    -> ONE accumulator per superpoint: [32 feat | 3 xyz | 1 count] = 36 f32.
//    50000 * 36 * 4B = 7.2 MB, fits in L2 -> atomics resolve at L2.
//  * red.global.add.v4.f32 (no-return vector reduction): 9 vector REDs per
//    point instead of 36 scalar atomicAdds.
//  * voxel gather (random 128B rows from 192MB table) issued FIRST so the
//    LDGs are in flight while the thread does the 32x32 MLP matmul.
// ---------------------------------------------------------------------------

#define N_SP_MAX   50000
#define ACC_STRIDE 36        // 36 floats = 144 B per superpoint, 16B-aligned rows
#define LN_EPS     1e-5f

__device__ __align__(16) float g_acc[N_SP_MAX * ACC_STRIDE];

// ---------------------------------------------------------------------------
__global__ void osp_zero_kernel(int n4) {
    int i = blockIdx.x * blockDim.x + threadIdx.x;
    if (i < n4) reinterpret_cast<float4*>(g_acc)[i] = make_float4(0.f, 0.f, 0.f, 0.f);
}

// Vectorized no-return global reduction (sm_90+).
__device__ __forceinline__ void red_add_v4(float* addr, float a, float b, float c, float d) {
    asm volatile("red.global.add.v4.f32 [%0], {%1, %2, %3, %4};"
                 :: "l"(addr), "f"(a), "f"(b), "f"(c), "f"(d)
                 : "memory");
}

// ---------------------------------------------------------------------------
__global__ __launch_bounds__(256)
void osp_point_kernel(const float* __restrict__ voxel_feats,
                      const float* __restrict__ xyz,
                      const float* __restrict__ W1,
                      const float* __restrict__ b1,
                      const float* __restrict__ gamma,
                      const float* __restrict__ beta,
                      const float* __restrict__ W2,
                      const float* __restrict__ b2,
                      const int*   __restrict__ p2v,
                      const int*   __restrict__ spid,
                      int n_points)
{
    __shared__ float sW1[96];
    __shared__ float sb1[32], sg[32], sbt[32], sb2[32];
    __shared__ float sW2[1024];

    for (int t = threadIdx.x; t < 96; t += blockDim.x) sW1[t] = W1[t];
    if (threadIdx.x < 32) {
        sb1[threadIdx.x] = b1[threadIdx.x];
        sg [threadIdx.x] = gamma[threadIdx.x];
        sbt[threadIdx.x] = beta[threadIdx.x];
        sb2[threadIdx.x] = b2[threadIdx.x];
    }
    for (int t = threadIdx.x; t < 1024; t += blockDim.x) sW2[t] = W2[t];
    __syncthreads();

    int i = blockIdx.x * blockDim.x + threadIdx.x;
    if (i >= n_points) return;

    // ---- issue the random gather first (latency overlapped with MLP) ----
    int v  = p2v[i];
    int sp = spid[i];
    const float4* vf = reinterpret_cast<const float4*>(voxel_feats + (size_t)v * 32);
    float4 gth[8];
#pragma unroll
    for (int j = 0; j < 8; j++) gth[j] = __ldg(vf + j);

    float px = xyz[3 * i + 0];
    float py = xyz[3 * i + 1];
    float pz = xyz[3 * i + 2];

    // ---- Linear(3,32) + LayerNorm + ReLU ----
    float h[32];
    float mu = 0.f;
#pragma unroll
    for (int c = 0; c < 32; c++) {
        float t = fmaf(px, sW1[c], fmaf(py, sW1[32 + c], fmaf(pz, sW1[64 + c], sb1[c])));
        h[c] = t;
        mu += t;
    }
    mu *= (1.f / 32.f);
    float var = 0.f;
#pragma unroll
    for (int c = 0; c < 32; c++) {
        float d = h[c] - mu;
        var = fmaf(d, d, var);
    }
    var *= (1.f / 32.f);
    float inv = rsqrtf(var + LN_EPS);
#pragma unroll
    for (int c = 0; c < 32; c++) {
        float t = fmaf((h[c] - mu) * inv, sg[c], sbt[c]);
        h[c] = fmaxf(t, 0.f);
    }

    // ---- Linear(32,32): out[c] = sum_k h[k] * W2[k][c] + b2[c] ----
    float4 o[8];
#pragma unroll
    for (int j = 0; j < 8; j++) o[j] = reinterpret_cast<const float4*>(sb2)[j];
#pragma unroll
    for (int k = 0; k < 32; k++) {
        float a = h[k];
        const float4* wr = reinterpret_cast<const float4*>(sW2 + k * 32);
#pragma unroll
        for (int j = 0; j < 8; j++) {
            float4 w = wr[j];
            o[j].x = fmaf(a, w.x, o[j].x);
            o[j].y = fmaf(a, w.y, o[j].y);
            o[j].z = fmaf(a, w.z, o[j].z);
            o[j].w = fmaf(a, w.w, o[j].w);
        }
    }

    // ---- fused scatter: feat(32) + xyz(3) + count(1) -> 9 x red.v4 ----
    float* base = g_acc + (size_t)sp * ACC_STRIDE;
#pragma unroll
    for (int j = 0; j < 8; j++) {
        red_add_v4(base + j * 4,
                   o[j].x + gth[j].x,
                   o[j].y + gth[j].y,
                   o[j].z + gth[j].z,
                   o[j].w + gth[j].w);
    }
    red_add_v4(base + 32, px, py, pz, 1.0f);
}

// ---------------------------------------------------------------------------
// out layout: [S*32 feat  |  S*3 xyz], all divided by max(count, 1).
__global__ void osp_finalize_kernel(float* __restrict__ out, int S) {
    int idx = blockIdx.x * blockDim.x + threadIdx.x;
    int total = S * 35;
    if (idx >= total) return;

    int featN = S * 32;
    int sp, col;
    if (idx < featN) {
        sp  = idx >> 5;
        col = idx & 31;
    } else {
        int r = idx - featN;
        sp  = r / 3;
        col = 32 + r % 3;
    }
    const float* base = g_acc + (size_t)sp * ACC_STRIDE;
    float den = fmaxf(base[35], 1.0f);
    out[idx] = base[col] / den;
}

// ---------------------------------------------------------------------------
extern "C" void kernel_launch(void* const* d_in, const int* in_sizes, int n_in,
                              void* d_out, int out_size)
{
    const float* voxel_feats = (const float*)d_in[0];
    const float* xyz         = (const float*)d_in[1];
    const float* W1          = (const float*)d_in[2];
    const float* b1          = (const float*)d_in[3];
    const float* gamma       = (const float*)d_in[4];
    const float* beta        = (const float*)d_in[5];
    const float* W2          = (const float*)d_in[6];
    const float* b2          = (const float*)d_in[7];
    const int*   p2v         = (const int*)d_in[8];
    const int*   spid        = (const int*)d_in[9];

    int n_points = in_sizes[8];          // p2v_map element count
    int S        = out_size / 35;        // S*32 feats + S*3 xyz
    if (S > N_SP_MAX) S = N_SP_MAX;

    // 1) zero accumulator (S * 36 floats; 36 % 4 == 0)
    int n4 = (S * ACC_STRIDE) / 4;
    osp_zero_kernel<<<(n4 + 255) / 256, 256>>>(n4);

    // 2) per-point fused gather + MLP + scatter
    osp_point_kernel<<<(n_points + 255) / 256, 256>>>(
        voxel_feats, xyz, W1, b1, gamma, beta, W2, b2, p2v, spid, n_points);

    // 3) divide by counts, write packed output
    int total = S * 35;
    osp_finalize_kernel<<<(total + 255) / 256, 256>>>((float*)d_out, S);
}